// round 14
// baseline (speedup 1.0000x reference)
#include <cuda_runtime.h>
#include <cstdint>

#define Bq 2
#define Cc 16
#define Hh 128
#define Ww 128
#define HWp (Hh*Ww)
#define TX 32
#define TY 8
#define NT 256
#define FNT 64

// packed 2xfp32 FMA: acc = x2*w + acc (both lanes, IEEE fp32 each)
#define FMA2(acc, x2, w) \
    asm("fma.rn.f32x2 %0, %1, %2, %0;" : "+l"(acc) : "l"(x2), "l"(w))
#define PACK2(dst, v) \
    asm("mov.b64 %0, {%1, %1};" : "=l"(dst) : "f"(v))
#define UNPACK2(lo, hi, src) \
    asm("mov.b64 {%0, %1}, %2;" : "=f"(lo), "=f"(hi) : "l"(src))

// cp.async helpers
__device__ __forceinline__ uint32_t smem_u32(const void* p) {
    return (uint32_t)__cvta_generic_to_shared(p);
}
#define CPA16(d, s)    asm volatile("cp.async.cg.shared.global [%0], [%1], 16;" :: "r"(d), "l"(s))
#define CPA4Z(d, s, z) asm volatile("cp.async.ca.shared.global [%0], [%1], 4, %2;" :: "r"(d), "l"(s), "r"(z))
#define CPCOMMIT()     asm volatile("cp.async.commit_group;" ::: "memory")
#define CPWAIT0()      asm volatile("cp.async.wait_group 0;" ::: "memory")

// ---------------- static device scratch (no allocations) ----------------
__device__ float g_att_bg[3][(size_t)Bq*64*HWp];          // 24 MB
__device__ float g_att_tg[3][(size_t)Bq*8*HWp];           // 3 MB
__device__ float g_feats[2][3][(size_t)Bq*Cc*HWp];        // 12 MB
__device__ float g_fold_part[6][Bq][64][Cc];              // per (group,b,tile) c-sums
__device__ float g_wt[2][Bq*3*Cc];
// transposed memory copies:
//   A-layout: [c][d][m]   (m contiguous)  -> for logits
//   B-layout: [m][d][c]   (c contiguous)  -> for fold
__device__ float g_memA_bg[3][64*Cc*49];
__device__ float g_memA_tg[3][8*Cc*49];
__device__ float g_memB_bg[3][64*Cc*49];
__device__ float g_memB_tg[3][8*Cc*49];

// ---------------- fused mem transpose (all 6 memories, one launch) ----------------
__global__ void transpose_all_kernel(const float* __restrict__ bm0, const float* __restrict__ bm1,
                                     const float* __restrict__ bm2, const float* __restrict__ tm0,
                                     const float* __restrict__ tm1, const float* __restrict__ tm2) {
    int g = blockIdx.y;
    const float* src; float* A; float* Bm; int M; int PP;
    switch (g) {
        case 0: src = bm2; A = g_memA_bg[2]; Bm = g_memB_bg[2]; M = 64; PP = 49; break;
        case 1: src = bm1; A = g_memA_bg[1]; Bm = g_memB_bg[1]; M = 64; PP = 25; break;
        case 2: src = bm0; A = g_memA_bg[0]; Bm = g_memB_bg[0]; M = 64; PP = 9;  break;
        case 3: src = tm2; A = g_memA_tg[2]; Bm = g_memB_tg[2]; M = 8;  PP = 49; break;
        case 4: src = tm1; A = g_memA_tg[1]; Bm = g_memB_tg[1]; M = 8;  PP = 25; break;
        default:src = tm0; A = g_memA_tg[0]; Bm = g_memB_tg[0]; M = 8;  PP = 9;  break;
    }
    int n = M*Cc*PP;
    for (int idx = blockIdx.x*blockDim.x + threadIdx.x; idx < n; idx += gridDim.x*blockDim.x) {
        int m   = idx / (Cc*PP);
        int rem = idx % (Cc*PP);
        int c   = rem / PP;
        int d   = rem % PP;
        float v = src[idx];
        A[(c*PP + d)*M + m]   = v;
        Bm[(m*PP + d)*Cc + c] = v;
    }
}

// ===== BG logits (R12 exact): 256 thr, 4 px x 16 m, f32x2 + cp.async double buffer =====
template<int P>
__device__ __forceinline__ void logits_bg_body(float* __restrict__ sb,
                                               const float* __restrict__ x,
                                               const float* __restrict__ memA,
                                               float* __restrict__ att,
                                               const float* __restrict__ temp,
                                               int b, int x0, int y0) {
    constexpr int PAD = P/2;
    constexpr int SW = TX + P - 1, SH = TY + P - 1;
    constexpr int PP = P*P;
    float* xs = sb;                 // [Cc][SH][SW]
    float* m0 = sb + Cc*SH*SW;      // [PP][64] stage 0
    float* m1 = m0 + PP*64;         // [PP][64] stage 1

    const int t  = threadIdx.x;
    const int tx = t & 31;
    const int w  = t >> 5;          // warp id 0..7
    const int tyg = w & 1;          // y group (rows tyg*4 .. +3)
    const int mg  = w >> 1;         // m group (16 m's)
    const int ty0 = tyg*4;

    // stage x tile with halo (zero-padded)
    for (int idx = t; idx < Cc*SH*SW; idx += NT) {
        int c = idx / (SH*SW);
        int r = idx % (SH*SW);
        int ry = r / SW, rx = r % SW;
        int gy = y0 + ry - PAD, gx = x0 + rx - PAD;
        float v = 0.f;
        if (gy >= 0 && gy < Hh && gx >= 0 && gx < Ww)
            v = x[((size_t)(b*Cc + c)*Hh + gy)*Ww + gx];
        xs[idx] = v;
    }
    // stage channel 0 weights
    {
        uint32_t md = smem_u32(m0);
        const float4* s4 = reinterpret_cast<const float4*>(memA);
        for (int idx = t; idx < PP*16; idx += NT) CPA16(md + (uint32_t)idx*16u, s4 + idx);
        CPCOMMIT();
    }
    CPWAIT0();
    __syncthreads();

    unsigned long long acc2[32];     // [k=4][pair=8]
    #pragma unroll
    for (int q = 0; q < 32; q++) acc2[q] = 0ull;

    for (int c = 0; c < Cc; c++) {
        float* cur = (c & 1) ? m1 : m0;
        if (c + 1 < Cc) {            // prefetch next channel while computing
            float* nxt = (c & 1) ? m0 : m1;
            uint32_t md = smem_u32(nxt);
            const float4* s4 = reinterpret_cast<const float4*>(memA + (size_t)(c+1)*PP*64);
            for (int idx = t; idx < PP*16; idx += NT) CPA16(md + (uint32_t)idx*16u, s4 + idx);
            CPCOMMIT();
        }
        const float* xc = xs + c*SH*SW;
        #pragma unroll 1
        for (int j = 0; j < P; j++) {
            float xr[P+3];
            #pragma unroll
            for (int r = 0; r < P+3; r++) xr[r] = xc[(ty0 + r)*SW + tx + j];
            #pragma unroll
            for (int i = 0; i < P; i++) {
                const ulonglong2* mp = reinterpret_cast<const ulonglong2*>(cur + (i*P + j)*64 + mg*16);
                ulonglong2 wA = mp[0], wB = mp[1], wC = mp[2], wD = mp[3];
                #pragma unroll
                for (int k = 0; k < 4; k++) {
                    unsigned long long x2;
                    PACK2(x2, xr[i + k]);
                    unsigned long long* a = acc2 + k*8;
                    FMA2(a[0], x2, wA.x); FMA2(a[1], x2, wA.y);
                    FMA2(a[2], x2, wB.x); FMA2(a[3], x2, wB.y);
                    FMA2(a[4], x2, wC.x); FMA2(a[5], x2, wC.y);
                    FMA2(a[6], x2, wD.x); FMA2(a[7], x2, wD.y);
                }
            }
        }
        CPWAIT0();
        __syncthreads();
    }

    // unpack to scalar
    float acc[64];
    #pragma unroll
    for (int q2 = 0; q2 < 32; q2++) {
        int k = q2 >> 3, q = q2 & 7;
        UNPACK2(acc[k*16 + 2*q], acc[k*16 + 2*q + 1], acc2[q2]);
    }

    // softmax over 64 m (reduce across 4 m-groups via smem)
    float scale = temp[0] / sqrtf((float)(Cc*PP));
    float* red  = xs;                // reuse xs (all compute done, last sync passed)
    float* red2 = xs + 1024;
    #pragma unroll
    for (int k = 0; k < 4; k++) {
        float mx = acc[k*16];
        #pragma unroll
        for (int m = 1; m < 16; m++) mx = fmaxf(mx, acc[k*16 + m]);
        red[(mg*8 + ty0 + k)*32 + tx] = mx;
    }
    __syncthreads();
    #pragma unroll
    for (int k = 0; k < 4; k++) {
        int row = (ty0 + k)*32 + tx;
        float mx = fmaxf(fmaxf(red[row], red[256 + row]), fmaxf(red[512 + row], red[768 + row]));
        float s = 0.f;
        #pragma unroll
        for (int m = 0; m < 16; m++) {
            acc[k*16 + m] = __expf(scale*(acc[k*16 + m] - mx));
            s += acc[k*16 + m];
        }
        red2[(mg*8 + ty0 + k)*32 + tx] = s;
    }
    __syncthreads();
    #pragma unroll
    for (int k = 0; k < 4; k++) {
        int row = (ty0 + k)*32 + tx;
        float s = red2[row] + red2[256 + row] + red2[512 + row] + red2[768 + row];
        float inv = 1.f / s;
        int gy = y0 + ty0 + k, gx = x0 + tx;
        #pragma unroll
        for (int m = 0; m < 16; m++)
            att[((size_t)(b*64 + mg*16 + m)*Hh + gy)*Ww + gx] = acc[k*16 + m]*inv;
    }
}

// ================= TG logits (M=8, scalar; small share of FLOPs) =================
template<int P, int M>
__device__ __forceinline__ void logits_tg_body(float* __restrict__ sb,
                                               const float* __restrict__ x,
                                               const float* __restrict__ memA,
                                               float* __restrict__ att,
                                               const float* __restrict__ temp,
                                               int b, int x0, int y0) {
    constexpr int PAD = P/2;
    constexpr int SW = TX + P - 1, SH = TY + P - 1;
    constexpr int PP = P*P;
    float* xs = sb;
    float* ms = sb + Cc*SH*SW;
    const int t  = threadIdx.x;
    const int tx = t & 31, ty = t >> 5;

    for (int idx = t; idx < Cc*SH*SW; idx += NT) {
        int c = idx / (SH*SW);
        int r = idx % (SH*SW);
        int ry = r / SW, rx = r % SW;
        int gy = y0 + ry - PAD, gx = x0 + rx - PAD;
        float v = 0.f;
        if (gy >= 0 && gy < Hh && gx >= 0 && gx < Ww)
            v = x[((size_t)(b*Cc + c)*Hh + gy)*Ww + gx];
        xs[idx] = v;
    }

    float acc[M];
    #pragma unroll
    for (int m = 0; m < M; m++) acc[m] = 0.f;

    for (int c = 0; c < Cc; c++) {
        __syncthreads();
        {
            const float4* s4 = reinterpret_cast<const float4*>(memA + (size_t)c*PP*M);
            float4* d4 = reinterpret_cast<float4*>(ms);
            for (int idx = t; idx < PP*M/4; idx += NT) d4[idx] = s4[idx];
        }
        __syncthreads();
        const float* xc = xs + c*SH*SW;
        for (int i = 0; i < P; i++) {
            for (int j = 0; j < P; j++) {
                float xv = xc[(ty + i)*SW + tx + j];
                const float4* mp = reinterpret_cast<const float4*>(ms + (i*P + j)*M);
                #pragma unroll
                for (int m4 = 0; m4 < M/4; m4++) {
                    float4 w = mp[m4];
                    acc[4*m4+0] = fmaf(xv, w.x, acc[4*m4+0]);
                    acc[4*m4+1] = fmaf(xv, w.y, acc[4*m4+1]);
                    acc[4*m4+2] = fmaf(xv, w.z, acc[4*m4+2]);
                    acc[4*m4+3] = fmaf(xv, w.w, acc[4*m4+3]);
                }
            }
        }
    }

    float scale = temp[0] / sqrtf((float)(Cc*PP));
    float mx = acc[0];
    #pragma unroll
    for (int m = 1; m < M; m++) mx = fmaxf(mx, acc[m]);
    float ssum = 0.f;
    #pragma unroll
    for (int m = 0; m < M; m++) { acc[m] = __expf(scale*(acc[m]-mx)); ssum += acc[m]; }
    float inv = 1.f / ssum;

    int gy = y0 + ty, gx = x0 + tx;
    #pragma unroll
    for (int m = 0; m < M; m++)
        att[((size_t)(b*M + m)*Hh + gy)*Ww + gx] = acc[m]*inv;
}

// p=7 bg worst case: xs 16*14*38 + 2 * (49*64) = 14784 floats
static constexpr int LOGITS_DYN = (16*14*38 + 2*49*64)*4;

__global__ __launch_bounds__(NT) void logits_all_kernel(
    const float* __restrict__ bg, const float* __restrict__ tg,
    const float* __restrict__ tb7, const float* __restrict__ tb5, const float* __restrict__ tb3,
    const float* __restrict__ tt7, const float* __restrict__ tt5, const float* __restrict__ tt3) {
    extern __shared__ __align__(16) float sb[];
    int blk = blockIdx.x;
    int group = blk >> 7;       // 128 blocks per group
    int r = blk & 127;
    int b = r >> 6;
    int tt = r & 63;
    int x0 = (tt & 3)*TX, y0 = (tt >> 2)*TY;
    switch (group) {
        case 0: logits_bg_body<7>(sb, bg, g_memA_bg[2], g_att_bg[2], tb7, b, x0, y0); break;
        case 1: logits_bg_body<5>(sb, bg, g_memA_bg[1], g_att_bg[1], tb5, b, x0, y0); break;
        case 2: logits_bg_body<3>(sb, bg, g_memA_bg[0], g_att_bg[0], tb3, b, x0, y0); break;
        case 3: logits_tg_body<7,8>(sb, tg, g_memA_tg[2], g_att_tg[2], tt7, b, x0, y0); break;
        case 4: logits_tg_body<5,8>(sb, tg, g_memA_tg[1], g_att_tg[1], tt5, b, x0, y0); break;
        default:logits_tg_body<3,8>(sb, tg, g_memA_tg[0], g_att_tg[0], tt3, b, x0, y0); break;
    }
}

// == fold: 32x8 tiles, 64-thread CTAs (2 warps), 4 px x 16 c per thread, f32x2 + cp.async
//    + fused pool partials in the epilogue ==
template<int P, int M, int MC>
__device__ __forceinline__ void fold2_body(float* __restrict__ sb,
                                           const float* __restrict__ att,
                                           const float* __restrict__ memB,
                                           float* __restrict__ feat,
                                           float* __restrict__ pool_out,
                                           int b, int x0, int y0) {
    constexpr int PAD = P/2;
    constexpr int SW = 32 + P - 1, SH = 8 + P - 1;
    constexpr int PP = P*P;
    constexpr int CHN = M/MC;
    constexpr int ASZ = MC*SH*SW;       // att tile floats per chunk
    constexpr int BSZ = MC*PP*16;       // weight floats per chunk
    float* buf0 = sb;
    float* buf1 = sb + (ASZ + BSZ);

    const int t  = threadIdx.x;
    const int tx = t & 31;
    const int w  = t >> 5;              // 0..1
    const int ty0 = w*4;                // warp -> 4 rows

    auto stage = [&](int mbase, float* buf) {
        uint32_t ad = smem_u32(buf);
        for (int idx = t; idx < ASZ; idx += FNT) {
            int ml = idx/(SH*SW); int r = idx%(SH*SW);
            int ry = r/SW, rx = r%SW;
            int gy = y0 + ry - PAD, gx = x0 + rx - PAD;
            bool ok = (gy >= 0 && gy < Hh && gx >= 0 && gx < Ww);
            const float* gp = att + ((size_t)(b*M + mbase + ml)*Hh + (ok ? gy : 0))*Ww + (ok ? gx : 0);
            CPA4Z(ad + (uint32_t)idx*4u, gp, ok ? 4 : 0);
        }
        uint32_t md = smem_u32(buf + ASZ);
        const float4* s4 = reinterpret_cast<const float4*>(memB + (size_t)mbase*PP*16);
        for (int idx = t; idx < BSZ/4; idx += FNT) CPA16(md + (uint32_t)idx*16u, s4 + idx);
        CPCOMMIT();
    };

    stage(0, buf0);
    CPWAIT0();
    __syncthreads();

    unsigned long long acc2[32];        // [k=4][pair=8], pair q = c (2q, 2q+1)
    #pragma unroll
    for (int q = 0; q < 32; q++) acc2[q] = 0ull;

    for (int ch = 0; ch < CHN; ch++) {
        float* cur = (ch & 1) ? buf1 : buf0;
        if (ch + 1 < CHN) stage((ch+1)*MC, (ch & 1) ? buf0 : buf1);
        #pragma unroll
        for (int ml = 0; ml < MC; ml++) {
            const float* am = cur + ml*SH*SW;
            const float* mb = cur + ASZ + ml*PP*16;
            #pragma unroll 1
            for (int j = 0; j < P; j++) {
                float ar[P+3];
                #pragma unroll
                for (int r = 0; r < P+3; r++) ar[r] = am[(ty0 + r)*SW + tx + j];
                #pragma unroll
                for (int i = 0; i < P; i++) {
                    const ulonglong2* mp = reinterpret_cast<const ulonglong2*>(mb + ((P-1-i)*P + (P-1-j))*16);
                    ulonglong2 wA = mp[0], wB = mp[1], wC = mp[2], wD = mp[3];
                    #pragma unroll
                    for (int k = 0; k < 4; k++) {
                        unsigned long long x2;
                        PACK2(x2, ar[i + k]);
                        unsigned long long* a = acc2 + k*8;
                        FMA2(a[0], x2, wA.x); FMA2(a[1], x2, wA.y);
                        FMA2(a[2], x2, wB.x); FMA2(a[3], x2, wB.y);
                        FMA2(a[4], x2, wC.x); FMA2(a[5], x2, wC.y);
                        FMA2(a[6], x2, wD.x); FMA2(a[7], x2, wD.y);
                    }
                }
            }
        }
        CPWAIT0();
        __syncthreads();
    }

    float acc[64];
    #pragma unroll
    for (int q2 = 0; q2 < 32; q2++) {
        int k = q2 >> 3, q = q2 & 7;
        UNPACK2(acc[k*16 + 2*q], acc[k*16 + 2*q + 1], acc2[q2]);
    }

    // store feats + per-thread channel sums of the outputs (fused pool)
    float csum[Cc];
    #pragma unroll
    for (int c = 0; c < Cc; c++) csum[c] = 0.f;
    #pragma unroll
    for (int k = 0; k < 4; k++) {
        int gy = y0 + ty0 + k, gx = x0 + tx;
        int cy = min(gy,PAD) + min(Hh-1-gy,PAD) + 1;   // analytic fold-of-ones divisor
        int cx = min(gx,PAD) + min(Ww-1-gx,PAD) + 1;
        float invd = 1.f/((float)(cy*cx) + 1e-8f);
        #pragma unroll
        for (int c = 0; c < Cc; c++) {
            float v = acc[k*16 + c]*invd;
            feat[((size_t)(b*Cc + c)*Hh + gy)*Ww + gx] = v;
            csum[c] += v;
        }
    }

    // reduce csum over 64 threads: shfl tree within warp, then 2-warp smem sum
    #pragma unroll
    for (int c = 0; c < Cc; c++) {
        #pragma unroll
        for (int off = 16; off > 0; off >>= 1)
            csum[c] += __shfl_xor_sync(0xffffffffu, csum[c], off);
    }
    float* wsum = buf0;     // safe: compute done, post-final-sync
    if (tx == 0) {
        #pragma unroll
        for (int c = 0; c < Cc; c++) wsum[w*Cc + c] = csum[c];
    }
    __syncthreads();
    if (t < Cc)
        pool_out[t] = wsum[t] + wsum[Cc + t];
}

// p=7 MC=4 worst: 2 * (4*14*38 + 4*49*16) = 10528 floats
static constexpr int FOLD_DYN = 2*(4*14*38 + 4*49*16)*4;

__global__ __launch_bounds__(FNT) void fold2_all_kernel() {
    extern __shared__ __align__(16) float sb[];
    int blk = blockIdx.x;
    int group = blk >> 7;       // 128 blocks per group (2 batches x 64 tiles of 32x8)
    int r = blk & 127;
    int b = r >> 6;
    int tt = r & 63;
    int x0 = (tt & 3)*32, y0 = (tt >> 2)*8;
    float* po = g_fold_part[group][b][tt];
    switch (group) {
        case 0: fold2_body<7,64,4>(sb, g_att_bg[2], g_memB_bg[2], g_feats[0][2], po, b, x0, y0); break;
        case 1: fold2_body<5,64,4>(sb, g_att_bg[1], g_memB_bg[1], g_feats[0][1], po, b, x0, y0); break;
        case 2: fold2_body<3,64,4>(sb, g_att_bg[0], g_memB_bg[0], g_feats[0][0], po, b, x0, y0); break;
        case 3: fold2_body<7,8,4> (sb, g_att_tg[2], g_memB_tg[2], g_feats[1][2], po, b, x0, y0); break;
        case 4: fold2_body<5,8,4> (sb, g_att_tg[1], g_memB_tg[1], g_feats[1][1], po, b, x0, y0); break;
        default:fold2_body<3,8,4> (sb, g_att_tg[0], g_memB_tg[0], g_feats[1][0], po, b, x0, y0); break;
    }
}

// ---------------- fusion (parallel partial-sum reduction, 256 threads) ----------------
__global__ void fuse_wt_kernel(const float* __restrict__ bw1, const float* __restrict__ bb1,
                               const float* __restrict__ bw2, const float* __restrict__ bb2,
                               const float* __restrict__ tw1, const float* __restrict__ tb1,
                               const float* __restrict__ tw2, const float* __restrict__ tb2) {
    __shared__ float part[64][4];
    __shared__ float pooled[2][32];
    int t = threadIdx.x;
    {   // each (branch,b,c) row gets 4 threads; each sums 48 of the 192 partials
        int row = t >> 2, seg = t & 3;
        int branch = row >> 5, r = row & 31;
        int b = r / Cc, c = r % Cc;
        float s = 0.f;
        for (int q = seg*48; q < seg*48 + 48; q++) {
            int g = q >> 6, tile = q & 63;
            s += g_fold_part[branch*3 + g][b][tile][c];
        }
        part[row][seg] = s;
    }
    __syncthreads();
    if (t < 64) {
        int branch = t >> 5, r = t & 31;
        pooled[branch][r] = (part[t][0] + part[t][1] + part[t][2] + part[t][3]) / (float)HWp;
    }
    __syncthreads();
    if (t >= 2*Bq*Cc) return;
    int branch = t / (Bq*Cc);
    int r = t % (Bq*Cc);
    int b = r / Cc, c = r % Cc;
    const float* w1 = branch ? tw1 : bw1;
    const float* b1 = branch ? tb1 : bb1;
    const float* w2 = branch ? tw2 : bw2;
    const float* b2 = branch ? tb2 : bb2;
    float hdn[4];
    for (int h = 0; h < 4; h++) {
        float sv = b1[h];
        for (int cc = 0; cc < Cc; cc++) sv += w1[h*Cc+cc] * pooled[branch][b*Cc+cc];
        hdn[h] = fmaxf(sv, 0.f);
    }
    float lg[3];
    for (int si = 0; si < 3; si++) {
        int row = si*Cc + c;
        float sv = b2[row];
        for (int h = 0; h < 4; h++) sv += w2[row*4+h]*hdn[h];
        lg[si] = sv;
    }
    float mx = fmaxf(lg[0], fmaxf(lg[1], lg[2]));
    float e0 = __expf(lg[0]-mx), e1 = __expf(lg[1]-mx), e2 = __expf(lg[2]-mx);
    float inv = 1.f/(e0+e1+e2);
    g_wt[branch][(b*3+0)*Cc+c] = e0*inv;
    g_wt[branch][(b*3+1)*Cc+c] = e1*inv;
    g_wt[branch][(b*3+2)*Cc+c] = e2*inv;
}

__global__ void combine_kernel(float* __restrict__ out) {
    const size_t N1 = (size_t)Bq*Cc*HWp;
    size_t idx = (size_t)blockIdx.x*blockDim.x + threadIdx.x;
    if (idx >= 2*N1) return;
    int branch = (int)(idx / N1);
    size_t r = idx % N1;
    int b = (int)(r / ((size_t)Cc*HWp));
    int c = (int)((r / HWp) % Cc);
    float w0 = g_wt[branch][(b*3+0)*Cc+c];
    float w1 = g_wt[branch][(b*3+1)*Cc+c];
    float w2 = g_wt[branch][(b*3+2)*Cc+c];
    out[idx] = g_feats[branch][0][r]*w0 + g_feats[branch][1][r]*w1 + g_feats[branch][2][r]*w2;
}

// ---------------- host launch ----------------
extern "C" void kernel_launch(void* const* d_in, const int* in_sizes, int n_in,
                              void* d_out, int out_size) {
    const float *bg = nullptr, *tg = nullptr;
    const float *bg_mem[3] = {}, *tg_mem[3] = {};
    const float *temp_bg[3] = {}, *temp_tg[3] = {};
    const float *f1w[2] = {}, *f1b[2] = {}, *f2w[2] = {}, *f2b[2] = {};
    int n_img = 0, n_t = 0, n_f1w = 0, n_f1b = 0, n_f2w = 0, n_f2b = 0;

    for (int i = 0; i < n_in; i++) {
        const float* p = (const float*)d_in[i];
        switch (in_sizes[i]) {
            case Bq*Cc*HWp: if (n_img++ == 0) bg = p; else tg = p; break;
            case 64*144: bg_mem[0] = p; break;
            case 64*400: bg_mem[1] = p; break;
            case 64*784: bg_mem[2] = p; break;
            case 8*144:  tg_mem[0] = p; break;
            case 8*400:  tg_mem[1] = p; break;
            case 8*784:  tg_mem[2] = p; break;
            case 1: {   // all temps identical (10.0) -> ordering-immune
                int k = n_t++;
                if (k < 6) { if (k % 2 == 0) temp_bg[k/2] = p; else temp_tg[k/2] = p; }
                break; }
            case 64:  { if (n_f1w < 2) f1w[n_f1w] = p; n_f1w++; break; }
            case 4:   { if (n_f1b < 2) f1b[n_f1b] = p; n_f1b++; break; }
            case 192: { if (n_f2w < 2) f2w[n_f2w] = p; n_f2w++; break; }
            case 48:  { if (n_f2b < 2) f2b[n_f2b] = p; n_f2b++; break; }
            default: break;
        }
    }

    // 1) transpose all memories (one launch)
    transpose_all_kernel<<<dim3(16,6), 256>>>(bg_mem[0], bg_mem[1], bg_mem[2],
                                              tg_mem[0], tg_mem[1], tg_mem[2]);

    // 2) sim + softmax -> att maps (256-thread CTAs, heavy first)
    cudaFuncSetAttribute(logits_all_kernel, cudaFuncAttributeMaxDynamicSharedMemorySize, LOGITS_DYN);
    logits_all_kernel<<<768, NT, LOGITS_DYN>>>(bg, tg,
                                               temp_bg[2], temp_bg[1], temp_bg[0],
                                               temp_tg[2], temp_tg[1], temp_tg[0]);

    // 3) readout + fold + divisor + fused pool partials (32x8 tiles, 768 blocks x 64 thr)
    cudaFuncSetAttribute(fold2_all_kernel, cudaFuncAttributeMaxDynamicSharedMemorySize, FOLD_DYN);
    fold2_all_kernel<<<768, FNT, FOLD_DYN>>>();

    // 4) fusion
    fuse_wt_kernel<<<1, 256>>>(f1w[0], f1b[0], f2w[0], f2b[0],
                               f1w[1], f1b[1], f2w[1], f2b[1]);
    const size_t Ntot = (size_t)2*Bq*Cc*HWp;
    combine_kernel<<<(unsigned)((Ntot + 255)/256), 256>>>((float*)d_out);
}

// round 15
// speedup vs baseline: 1.0728x; 1.0728x over previous
#include <cuda_runtime.h>
#include <cstdint>

#define Bq 2
#define Cc 16
#define Hh 128
#define Ww 128
#define HWp (Hh*Ww)
#define TX 32
#define TY 8
#define NT 256
#define FNT 128

// packed 2xfp32 FMA: acc = x2*w + acc (both lanes, IEEE fp32 each)
#define FMA2(acc, x2, w) \
    asm("fma.rn.f32x2 %0, %1, %2, %0;" : "+l"(acc) : "l"(x2), "l"(w))
#define PACK2(dst, v) \
    asm("mov.b64 %0, {%1, %1};" : "=l"(dst) : "f"(v))
#define UNPACK2(lo, hi, src) \
    asm("mov.b64 {%0, %1}, %2;" : "=f"(lo), "=f"(hi) : "l"(src))

// cp.async helpers
__device__ __forceinline__ uint32_t smem_u32(const void* p) {
    return (uint32_t)__cvta_generic_to_shared(p);
}
#define CPA16(d, s)    asm volatile("cp.async.cg.shared.global [%0], [%1], 16;" :: "r"(d), "l"(s))
#define CPA4Z(d, s, z) asm volatile("cp.async.ca.shared.global [%0], [%1], 4, %2;" :: "r"(d), "l"(s), "r"(z))
#define CPCOMMIT()     asm volatile("cp.async.commit_group;" ::: "memory")
#define CPWAIT0()      asm volatile("cp.async.wait_group 0;" ::: "memory")

// ---------------- static device scratch (no allocations) ----------------
__device__ float g_att_bg[3][(size_t)Bq*64*HWp];          // 24 MB
__device__ float g_att_tg[3][(size_t)Bq*8*HWp];           // 3 MB
__device__ float g_feats[2][3][(size_t)Bq*Cc*HWp];        // 12 MB
__device__ float g_fold_part[6][Bq][64][Cc];              // per (group,b,tile) c-sums
__device__ float g_wt[2][Bq*3*Cc];
// transposed memory copies:
//   A-layout: [c][d][m]   (m contiguous)  -> for logits
//   B-layout: [m][d][c]   (c contiguous)  -> for fold
__device__ float g_memA_bg[3][64*Cc*49];
__device__ float g_memA_tg[3][8*Cc*49];
__device__ float g_memB_bg[3][64*Cc*49];
__device__ float g_memB_tg[3][8*Cc*49];

// ---------------- fused mem transpose (all 6 memories, one launch) ----------------
__global__ void transpose_all_kernel(const float* __restrict__ bm0, const float* __restrict__ bm1,
                                     const float* __restrict__ bm2, const float* __restrict__ tm0,
                                     const float* __restrict__ tm1, const float* __restrict__ tm2) {
    int g = blockIdx.y;
    const float* src; float* A; float* Bm; int M; int PP;
    switch (g) {
        case 0: src = bm2; A = g_memA_bg[2]; Bm = g_memB_bg[2]; M = 64; PP = 49; break;
        case 1: src = bm1; A = g_memA_bg[1]; Bm = g_memB_bg[1]; M = 64; PP = 25; break;
        case 2: src = bm0; A = g_memA_bg[0]; Bm = g_memB_bg[0]; M = 64; PP = 9;  break;
        case 3: src = tm2; A = g_memA_tg[2]; Bm = g_memB_tg[2]; M = 8;  PP = 49; break;
        case 4: src = tm1; A = g_memA_tg[1]; Bm = g_memB_tg[1]; M = 8;  PP = 25; break;
        default:src = tm0; A = g_memA_tg[0]; Bm = g_memB_tg[0]; M = 8;  PP = 9;  break;
    }
    int n = M*Cc*PP;
    for (int idx = blockIdx.x*blockDim.x + threadIdx.x; idx < n; idx += gridDim.x*blockDim.x) {
        int m   = idx / (Cc*PP);
        int rem = idx % (Cc*PP);
        int c   = rem / PP;
        int d   = rem % PP;
        float v = src[idx];
        A[(c*PP + d)*M + m]   = v;
        Bm[(m*PP + d)*Cc + c] = v;
    }
}

// ===== BG logits (R12 exact): 256 thr, 4 px x 16 m, f32x2 + cp.async double buffer =====
template<int P>
__device__ __forceinline__ void logits_bg_body(float* __restrict__ sb,
                                               const float* __restrict__ x,
                                               const float* __restrict__ memA,
                                               float* __restrict__ att,
                                               const float* __restrict__ temp,
                                               int b, int x0, int y0) {
    constexpr int PAD = P/2;
    constexpr int SW = TX + P - 1, SH = TY + P - 1;
    constexpr int PP = P*P;
    float* xs = sb;                 // [Cc][SH][SW]
    float* m0 = sb + Cc*SH*SW;      // [PP][64] stage 0
    float* m1 = m0 + PP*64;         // [PP][64] stage 1

    const int t  = threadIdx.x;
    const int tx = t & 31;
    const int w  = t >> 5;          // warp id 0..7
    const int tyg = w & 1;          // y group (rows tyg*4 .. +3)
    const int mg  = w >> 1;         // m group (16 m's)
    const int ty0 = tyg*4;

    // stage x tile with halo (zero-padded)
    for (int idx = t; idx < Cc*SH*SW; idx += NT) {
        int c = idx / (SH*SW);
        int r = idx % (SH*SW);
        int ry = r / SW, rx = r % SW;
        int gy = y0 + ry - PAD, gx = x0 + rx - PAD;
        float v = 0.f;
        if (gy >= 0 && gy < Hh && gx >= 0 && gx < Ww)
            v = x[((size_t)(b*Cc + c)*Hh + gy)*Ww + gx];
        xs[idx] = v;
    }
    // stage channel 0 weights
    {
        uint32_t md = smem_u32(m0);
        const float4* s4 = reinterpret_cast<const float4*>(memA);
        for (int idx = t; idx < PP*16; idx += NT) CPA16(md + (uint32_t)idx*16u, s4 + idx);
        CPCOMMIT();
    }
    CPWAIT0();
    __syncthreads();

    unsigned long long acc2[32];     // [k=4][pair=8]
    #pragma unroll
    for (int q = 0; q < 32; q++) acc2[q] = 0ull;

    for (int c = 0; c < Cc; c++) {
        float* cur = (c & 1) ? m1 : m0;
        if (c + 1 < Cc) {            // prefetch next channel while computing
            float* nxt = (c & 1) ? m0 : m1;
            uint32_t md = smem_u32(nxt);
            const float4* s4 = reinterpret_cast<const float4*>(memA + (size_t)(c+1)*PP*64);
            for (int idx = t; idx < PP*16; idx += NT) CPA16(md + (uint32_t)idx*16u, s4 + idx);
            CPCOMMIT();
        }
        const float* xc = xs + c*SH*SW;
        #pragma unroll 1
        for (int j = 0; j < P; j++) {
            float xr[P+3];
            #pragma unroll
            for (int r = 0; r < P+3; r++) xr[r] = xc[(ty0 + r)*SW + tx + j];
            #pragma unroll
            for (int i = 0; i < P; i++) {
                const ulonglong2* mp = reinterpret_cast<const ulonglong2*>(cur + (i*P + j)*64 + mg*16);
                ulonglong2 wA = mp[0], wB = mp[1], wC = mp[2], wD = mp[3];
                #pragma unroll
                for (int k = 0; k < 4; k++) {
                    unsigned long long x2;
                    PACK2(x2, xr[i + k]);
                    unsigned long long* a = acc2 + k*8;
                    FMA2(a[0], x2, wA.x); FMA2(a[1], x2, wA.y);
                    FMA2(a[2], x2, wB.x); FMA2(a[3], x2, wB.y);
                    FMA2(a[4], x2, wC.x); FMA2(a[5], x2, wC.y);
                    FMA2(a[6], x2, wD.x); FMA2(a[7], x2, wD.y);
                }
            }
        }
        CPWAIT0();
        __syncthreads();
    }

    // unpack to scalar
    float acc[64];
    #pragma unroll
    for (int q2 = 0; q2 < 32; q2++) {
        int k = q2 >> 3, q = q2 & 7;
        UNPACK2(acc[k*16 + 2*q], acc[k*16 + 2*q + 1], acc2[q2]);
    }

    // softmax over 64 m (reduce across 4 m-groups via smem)
    float scale = temp[0] / sqrtf((float)(Cc*PP));
    float* red  = xs;                // reuse xs (all compute done, last sync passed)
    float* red2 = xs + 1024;
    #pragma unroll
    for (int k = 0; k < 4; k++) {
        float mx = acc[k*16];
        #pragma unroll
        for (int m = 1; m < 16; m++) mx = fmaxf(mx, acc[k*16 + m]);
        red[(mg*8 + ty0 + k)*32 + tx] = mx;
    }
    __syncthreads();
    #pragma unroll
    for (int k = 0; k < 4; k++) {
        int row = (ty0 + k)*32 + tx;
        float mx = fmaxf(fmaxf(red[row], red[256 + row]), fmaxf(red[512 + row], red[768 + row]));
        float s = 0.f;
        #pragma unroll
        for (int m = 0; m < 16; m++) {
            acc[k*16 + m] = __expf(scale*(acc[k*16 + m] - mx));
            s += acc[k*16 + m];
        }
        red2[(mg*8 + ty0 + k)*32 + tx] = s;
    }
    __syncthreads();
    #pragma unroll
    for (int k = 0; k < 4; k++) {
        int row = (ty0 + k)*32 + tx;
        float s = red2[row] + red2[256 + row] + red2[512 + row] + red2[768 + row];
        float inv = 1.f / s;
        int gy = y0 + ty0 + k, gx = x0 + tx;
        #pragma unroll
        for (int m = 0; m < 16; m++)
            att[((size_t)(b*64 + mg*16 + m)*Hh + gy)*Ww + gx] = acc[k*16 + m]*inv;
    }
}

// ================= TG logits (M=8, scalar; small share of FLOPs) =================
template<int P, int M>
__device__ __forceinline__ void logits_tg_body(float* __restrict__ sb,
                                               const float* __restrict__ x,
                                               const float* __restrict__ memA,
                                               float* __restrict__ att,
                                               const float* __restrict__ temp,
                                               int b, int x0, int y0) {
    constexpr int PAD = P/2;
    constexpr int SW = TX + P - 1, SH = TY + P - 1;
    constexpr int PP = P*P;
    float* xs = sb;
    float* ms = sb + Cc*SH*SW;
    const int t  = threadIdx.x;
    const int tx = t & 31, ty = t >> 5;

    for (int idx = t; idx < Cc*SH*SW; idx += NT) {
        int c = idx / (SH*SW);
        int r = idx % (SH*SW);
        int ry = r / SW, rx = r % SW;
        int gy = y0 + ry - PAD, gx = x0 + rx - PAD;
        float v = 0.f;
        if (gy >= 0 && gy < Hh && gx >= 0 && gx < Ww)
            v = x[((size_t)(b*Cc + c)*Hh + gy)*Ww + gx];
        xs[idx] = v;
    }

    float acc[M];
    #pragma unroll
    for (int m = 0; m < M; m++) acc[m] = 0.f;

    for (int c = 0; c < Cc; c++) {
        __syncthreads();
        {
            const float4* s4 = reinterpret_cast<const float4*>(memA + (size_t)c*PP*M);
            float4* d4 = reinterpret_cast<float4*>(ms);
            for (int idx = t; idx < PP*M/4; idx += NT) d4[idx] = s4[idx];
        }
        __syncthreads();
        const float* xc = xs + c*SH*SW;
        for (int i = 0; i < P; i++) {
            for (int j = 0; j < P; j++) {
                float xv = xc[(ty + i)*SW + tx + j];
                const float4* mp = reinterpret_cast<const float4*>(ms + (i*P + j)*M);
                #pragma unroll
                for (int m4 = 0; m4 < M/4; m4++) {
                    float4 w = mp[m4];
                    acc[4*m4+0] = fmaf(xv, w.x, acc[4*m4+0]);
                    acc[4*m4+1] = fmaf(xv, w.y, acc[4*m4+1]);
                    acc[4*m4+2] = fmaf(xv, w.z, acc[4*m4+2]);
                    acc[4*m4+3] = fmaf(xv, w.w, acc[4*m4+3]);
                }
            }
        }
    }

    float scale = temp[0] / sqrtf((float)(Cc*PP));
    float mx = acc[0];
    #pragma unroll
    for (int m = 1; m < M; m++) mx = fmaxf(mx, acc[m]);
    float ssum = 0.f;
    #pragma unroll
    for (int m = 0; m < M; m++) { acc[m] = __expf(scale*(acc[m]-mx)); ssum += acc[m]; }
    float inv = 1.f / ssum;

    int gy = y0 + ty, gx = x0 + tx;
    #pragma unroll
    for (int m = 0; m < M; m++)
        att[((size_t)(b*M + m)*Hh + gy)*Ww + gx] = acc[m]*inv;
}

// p=7 bg worst case: xs 16*14*38 + 2 * (49*64) = 14784 floats
static constexpr int LOGITS_DYN = (16*14*38 + 2*49*64)*4;

__global__ __launch_bounds__(NT) void logits_all_kernel(
    const float* __restrict__ bg, const float* __restrict__ tg,
    const float* __restrict__ tb7, const float* __restrict__ tb5, const float* __restrict__ tb3,
    const float* __restrict__ tt7, const float* __restrict__ tt5, const float* __restrict__ tt3) {
    extern __shared__ __align__(16) float sb[];
    int blk = blockIdx.x;
    int group = blk >> 7;       // 128 blocks per group
    int r = blk & 127;
    int b = r >> 6;
    int tt = r & 63;
    int x0 = (tt & 3)*TX, y0 = (tt >> 2)*TY;
    switch (group) {
        case 0: logits_bg_body<7>(sb, bg, g_memA_bg[2], g_att_bg[2], tb7, b, x0, y0); break;
        case 1: logits_bg_body<5>(sb, bg, g_memA_bg[1], g_att_bg[1], tb5, b, x0, y0); break;
        case 2: logits_bg_body<3>(sb, bg, g_memA_bg[0], g_att_bg[0], tb3, b, x0, y0); break;
        case 3: logits_tg_body<7,8>(sb, tg, g_memA_tg[2], g_att_tg[2], tt7, b, x0, y0); break;
        case 4: logits_tg_body<5,8>(sb, tg, g_memA_tg[1], g_att_tg[1], tt5, b, x0, y0); break;
        default:logits_tg_body<3,8>(sb, tg, g_memA_tg[0], g_att_tg[0], tt3, b, x0, y0); break;
    }
}

// == fold (R12 exact): 32x8 tiles, 128-thr CTAs, 2 px x 16 c, f32x2 + cp.async
//    + fused pool partials in the epilogue ==
template<int P, int M, int MC>
__device__ __forceinline__ void fold2_body(float* __restrict__ sb,
                                           const float* __restrict__ att,
                                           const float* __restrict__ memB,
                                           float* __restrict__ feat,
                                           float* __restrict__ pool_out,
                                           int b, int x0, int y0) {
    constexpr int PAD = P/2;
    constexpr int SW = 32 + P - 1, SH = 8 + P - 1;
    constexpr int PP = P*P;
    constexpr int CHN = M/MC;
    constexpr int ASZ = MC*SH*SW;       // att tile floats per chunk
    constexpr int BSZ = MC*PP*16;       // weight floats per chunk
    float* buf0 = sb;
    float* buf1 = sb + (ASZ + BSZ);

    const int t  = threadIdx.x;
    const int tx = t & 31;
    const int w  = t >> 5;
    const int ty0 = w*2;                // warp -> 2 rows

    auto stage = [&](int mbase, float* buf) {
        uint32_t ad = smem_u32(buf);
        for (int idx = t; idx < ASZ; idx += FNT) {
            int ml = idx/(SH*SW); int r = idx%(SH*SW);
            int ry = r/SW, rx = r%SW;
            int gy = y0 + ry - PAD, gx = x0 + rx - PAD;
            bool ok = (gy >= 0 && gy < Hh && gx >= 0 && gx < Ww);
            const float* gp = att + ((size_t)(b*M + mbase + ml)*Hh + (ok ? gy : 0))*Ww + (ok ? gx : 0);
            CPA4Z(ad + (uint32_t)idx*4u, gp, ok ? 4 : 0);
        }
        uint32_t md = smem_u32(buf + ASZ);
        const float4* s4 = reinterpret_cast<const float4*>(memB + (size_t)mbase*PP*16);
        for (int idx = t; idx < BSZ/4; idx += FNT) CPA16(md + (uint32_t)idx*16u, s4 + idx);
        CPCOMMIT();
    };

    stage(0, buf0);
    CPWAIT0();
    __syncthreads();

    unsigned long long acc2[16];        // [k=2][pair=8], pair q = c (2q, 2q+1)
    #pragma unroll
    for (int q = 0; q < 16; q++) acc2[q] = 0ull;

    for (int ch = 0; ch < CHN; ch++) {
        float* cur = (ch & 1) ? buf1 : buf0;
        if (ch + 1 < CHN) stage((ch+1)*MC, (ch & 1) ? buf0 : buf1);
        #pragma unroll
        for (int ml = 0; ml < MC; ml++) {
            const float* am = cur + ml*SH*SW;
            const float* mb = cur + ASZ + ml*PP*16;
            #pragma unroll 1
            for (int j = 0; j < P; j++) {
                float ar[P+1];
                #pragma unroll
                for (int r = 0; r < P+1; r++) ar[r] = am[(ty0 + r)*SW + tx + j];
                #pragma unroll
                for (int i = 0; i < P; i++) {
                    const ulonglong2* mp = reinterpret_cast<const ulonglong2*>(mb + ((P-1-i)*P + (P-1-j))*16);
                    ulonglong2 wA = mp[0], wB = mp[1], wC = mp[2], wD = mp[3];
                    #pragma unroll
                    for (int k = 0; k < 2; k++) {
                        unsigned long long x2;
                        PACK2(x2, ar[i + k]);
                        unsigned long long* a = acc2 + k*8;
                        FMA2(a[0], x2, wA.x); FMA2(a[1], x2, wA.y);
                        FMA2(a[2], x2, wB.x); FMA2(a[3], x2, wB.y);
                        FMA2(a[4], x2, wC.x); FMA2(a[5], x2, wC.y);
                        FMA2(a[6], x2, wD.x); FMA2(a[7], x2, wD.y);
                    }
                }
            }
        }
        CPWAIT0();
        __syncthreads();
    }

    float acc[32];
    #pragma unroll
    for (int q2 = 0; q2 < 16; q2++) {
        int k = q2 >> 3, q = q2 & 7;
        UNPACK2(acc[k*16 + 2*q], acc[k*16 + 2*q + 1], acc2[q2]);
    }

    // store feats + per-thread channel sums of the outputs (fused pool)
    float csum[Cc];
    #pragma unroll
    for (int c = 0; c < Cc; c++) csum[c] = 0.f;
    #pragma unroll
    for (int k = 0; k < 2; k++) {
        int gy = y0 + ty0 + k, gx = x0 + tx;
        int cy = min(gy,PAD) + min(Hh-1-gy,PAD) + 1;   // analytic fold-of-ones divisor
        int cx = min(gx,PAD) + min(Ww-1-gx,PAD) + 1;
        float invd = 1.f/((float)(cy*cx) + 1e-8f);
        #pragma unroll
        for (int c = 0; c < Cc; c++) {
            float v = acc[k*16 + c]*invd;
            feat[((size_t)(b*Cc + c)*Hh + gy)*Ww + gx] = v;
            csum[c] += v;
        }
    }

    // reduce csum over 128 threads: shfl tree within warp, then 4-warp smem sum
    #pragma unroll
    for (int c = 0; c < Cc; c++) {
        #pragma unroll
        for (int off = 16; off > 0; off >>= 1)
            csum[c] += __shfl_xor_sync(0xffffffffu, csum[c], off);
    }
    float* wsum = buf0;     // safe: compute done, post-final-sync
    if (tx == 0) {
        #pragma unroll
        for (int c = 0; c < Cc; c++) wsum[w*Cc + c] = csum[c];
    }
    __syncthreads();
    if (t < Cc)
        pool_out[t] = wsum[t] + wsum[Cc + t] + wsum[2*Cc + t] + wsum[3*Cc + t];
}

// p=7 MC=4 worst: 2 * (4*14*38 + 4*49*16) = 10528 floats
static constexpr int FOLD_DYN = 2*(4*14*38 + 4*49*16)*4;

__global__ __launch_bounds__(FNT) void fold2_all_kernel() {
    extern __shared__ __align__(16) float sb[];
    int blk = blockIdx.x;
    int group = blk >> 7;       // 128 blocks per group (2 batches x 64 tiles of 32x8)
    int r = blk & 127;
    int b = r >> 6;
    int tt = r & 63;
    int x0 = (tt & 3)*32, y0 = (tt >> 2)*8;
    float* po = g_fold_part[group][b][tt];
    switch (group) {
        case 0: fold2_body<7,64,4>(sb, g_att_bg[2], g_memB_bg[2], g_feats[0][2], po, b, x0, y0); break;
        case 1: fold2_body<5,64,4>(sb, g_att_bg[1], g_memB_bg[1], g_feats[0][1], po, b, x0, y0); break;
        case 2: fold2_body<3,64,4>(sb, g_att_bg[0], g_memB_bg[0], g_feats[0][0], po, b, x0, y0); break;
        case 3: fold2_body<7,8,4> (sb, g_att_tg[2], g_memB_tg[2], g_feats[1][2], po, b, x0, y0); break;
        case 4: fold2_body<5,8,4> (sb, g_att_tg[1], g_memB_tg[1], g_feats[1][1], po, b, x0, y0); break;
        default:fold2_body<3,8,4> (sb, g_att_tg[0], g_memB_tg[0], g_feats[1][0], po, b, x0, y0); break;
    }
}

// ---------------- fusion (parallel partial-sum reduction, 256 threads) ----------------
__global__ void fuse_wt_kernel(const float* __restrict__ bw1, const float* __restrict__ bb1,
                               const float* __restrict__ bw2, const float* __restrict__ bb2,
                               const float* __restrict__ tw1, const float* __restrict__ tb1,
                               const float* __restrict__ tw2, const float* __restrict__ tb2) {
    __shared__ float part[64][4];
    __shared__ float pooled[2][32];
    int t = threadIdx.x;
    {   // each (branch,b,c) row gets 4 threads; each sums 48 of the 192 partials
        int row = t >> 2, seg = t & 3;
        int branch = row >> 5, r = row & 31;
        int b = r / Cc, c = r % Cc;
        float s = 0.f;
        for (int q = seg*48; q < seg*48 + 48; q++) {
            int g = q >> 6, tile = q & 63;
            s += g_fold_part[branch*3 + g][b][tile][c];
        }
        part[row][seg] = s;
    }
    __syncthreads();
    if (t < 64) {
        int branch = t >> 5, r = t & 31;
        pooled[branch][r] = (part[t][0] + part[t][1] + part[t][2] + part[t][3]) / (float)HWp;
    }
    __syncthreads();
    if (t >= 2*Bq*Cc) return;
    int branch = t / (Bq*Cc);
    int r = t % (Bq*Cc);
    int b = r / Cc, c = r % Cc;
    const float* w1 = branch ? tw1 : bw1;
    const float* b1 = branch ? tb1 : bb1;
    const float* w2 = branch ? tw2 : bw2;
    const float* b2 = branch ? tb2 : bb2;
    float hdn[4];
    for (int h = 0; h < 4; h++) {
        float sv = b1[h];
        for (int cc = 0; cc < Cc; cc++) sv += w1[h*Cc+cc] * pooled[branch][b*Cc+cc];
        hdn[h] = fmaxf(sv, 0.f);
    }
    float lg[3];
    for (int si = 0; si < 3; si++) {
        int row = si*Cc + c;
        float sv = b2[row];
        for (int h = 0; h < 4; h++) sv += w2[row*4+h]*hdn[h];
        lg[si] = sv;
    }
    float mx = fmaxf(lg[0], fmaxf(lg[1], lg[2]));
    float e0 = __expf(lg[0]-mx), e1 = __expf(lg[1]-mx), e2 = __expf(lg[2]-mx);
    float inv = 1.f/(e0+e1+e2);
    g_wt[branch][(b*3+0)*Cc+c] = e0*inv;
    g_wt[branch][(b*3+1)*Cc+c] = e1*inv;
    g_wt[branch][(b*3+2)*Cc+c] = e2*inv;
}

// ---------------- combine (float4 vectorized; identical per-element math) ----------------
__global__ void combine_kernel(float4* __restrict__ out) {
    const size_t N1 = (size_t)Bq*Cc*HWp;
    const size_t N4 = 2*N1/4;
    size_t idx = (size_t)blockIdx.x*blockDim.x + threadIdx.x;
    if (idx >= N4) return;
    size_t e = idx*4;
    int branch = (int)(e / N1);
    size_t r = e % N1;
    int b = (int)(r / ((size_t)Cc*HWp));
    int c = (int)((r / HWp) % Cc);      // constant across the 4 elems (HWp % 4 == 0)
    float w0 = g_wt[branch][(b*3+0)*Cc+c];
    float w1 = g_wt[branch][(b*3+1)*Cc+c];
    float w2 = g_wt[branch][(b*3+2)*Cc+c];
    size_t r4 = r >> 2;
    float4 f0 = reinterpret_cast<const float4*>(g_feats[branch][0])[r4];
    float4 f1 = reinterpret_cast<const float4*>(g_feats[branch][1])[r4];
    float4 f2 = reinterpret_cast<const float4*>(g_feats[branch][2])[r4];
    float4 o;
    o.x = f0.x*w0 + f1.x*w1 + f2.x*w2;
    o.y = f0.y*w0 + f1.y*w1 + f2.y*w2;
    o.z = f0.z*w0 + f1.z*w1 + f2.z*w2;
    o.w = f0.w*w0 + f1.w*w1 + f2.w*w2;
    out[idx] = o;
}

// ---------------- host launch ----------------
extern "C" void kernel_launch(void* const* d_in, const int* in_sizes, int n_in,
                              void* d_out, int out_size) {
    const float *bg = nullptr, *tg = nullptr;
    const float *bg_mem[3] = {}, *tg_mem[3] = {};
    const float *temp_bg[3] = {}, *temp_tg[3] = {};
    const float *f1w[2] = {}, *f1b[2] = {}, *f2w[2] = {}, *f2b[2] = {};
    int n_img = 0, n_t = 0, n_f1w = 0, n_f1b = 0, n_f2w = 0, n_f2b = 0;

    for (int i = 0; i < n_in; i++) {
        const float* p = (const float*)d_in[i];
        switch (in_sizes[i]) {
            case Bq*Cc*HWp: if (n_img++ == 0) bg = p; else tg = p; break;
            case 64*144: bg_mem[0] = p; break;
            case 64*400: bg_mem[1] = p; break;
            case 64*784: bg_mem[2] = p; break;
            case 8*144:  tg_mem[0] = p; break;
            case 8*400:  tg_mem[1] = p; break;
            case 8*784:  tg_mem[2] = p; break;
            case 1: {   // all temps identical (10.0) -> ordering-immune
                int k = n_t++;
                if (k < 6) { if (k % 2 == 0) temp_bg[k/2] = p; else temp_tg[k/2] = p; }
                break; }
            case 64:  { if (n_f1w < 2) f1w[n_f1w] = p; n_f1w++; break; }
            case 4:   { if (n_f1b < 2) f1b[n_f1b] = p; n_f1b++; break; }
            case 192: { if (n_f2w < 2) f2w[n_f2w] = p; n_f2w++; break; }
            case 48:  { if (n_f2b < 2) f2b[n_f2b] = p; n_f2b++; break; }
            default: break;
        }
    }

    // 1) transpose all memories (one launch)
    transpose_all_kernel<<<dim3(16,6), 256>>>(bg_mem[0], bg_mem[1], bg_mem[2],
                                              tg_mem[0], tg_mem[1], tg_mem[2]);

    // 2) sim + softmax -> att maps (256-thread CTAs, heavy first)
    cudaFuncSetAttribute(logits_all_kernel, cudaFuncAttributeMaxDynamicSharedMemorySize, LOGITS_DYN);
    logits_all_kernel<<<768, NT, LOGITS_DYN>>>(bg, tg,
                                               temp_bg[2], temp_bg[1], temp_bg[0],
                                               temp_tg[2], temp_tg[1], temp_tg[0]);

    // 3) readout + fold + divisor + fused pool partials (32x8 tiles, 768 blocks)
    cudaFuncSetAttribute(fold2_all_kernel, cudaFuncAttributeMaxDynamicSharedMemorySize, FOLD_DYN);
    fold2_all_kernel<<<768, FNT, FOLD_DYN>>>();

    // 4) fusion
    fuse_wt_kernel<<<1, 256>>>(f1w[0], f1b[0], f2w[0], f2b[0],
                               f1w[1], f1b[1], f2w[1], f2b[1]);
    const size_t N4 = (size_t)2*Bq*Cc*HWp/4;
    combine_kernel<<<(unsigned)((N4 + 255)/256), 256>>>((float4*)d_out);
}